// round 17
// baseline (speedup 1.0000x reference)
#include <cuda_runtime.h>

// BioSelfAttention — fused, closed-form LIF, exact all-zero fast exit.
// Launch-shape experiment: grid 128 x block 256 (4 CTAs per (b,h) slice).
// Front end (dots -> LIF -> WTA-3D) is computed redundantly per CTA (Q/K
// re-reads hit L2), so CTAs never communicate. Fast path stores only this
// CTA's quarter; slow path computes the full stage D/E redundantly and all
// four CTAs store bitwise-identical values (benign duplicate stores).
//
// WTA step: x_i <- clip(3*x_i - 0.9*S, 0, 1), S = sum x (W = inh + (exc-inh)I).
// Exact fixed points => bitwise-stationary early exit is numerically exact.
// LIF closed form: spikes periodic, t1 = ceil(ln(1-1/J)/ln 0.95),
// count over 100 steps = floor(100/t1). Rates feed only the massively
// saturated WTA, so __logf's ulp-level error cannot change the fixed point.

#define NBH 32

__device__ __forceinline__ float lif_rate_cf(float J) {
    if (J <= 1.0f) return 0.0f;                      // v_inf = J < 1: no spike
    float ratio = __logf(1.0f - 1.0f / J) * (-19.4957257f);  // 1/ln(0.95)
    if (!(ratio <= 100.0f)) return 0.0f;             // no spike in 100 steps
    int t1 = (int)ceilf(ratio);
    if (t1 < 1) t1 = 1;
    return (float)(100 / t1) * 0.01f;                // floor(100/t1)/100
}

__global__ void __launch_bounds__(256)
k_bio_fused(const float* __restrict__ Q, const float* __restrict__ K,
            const float* __restrict__ V, float* __restrict__ out) {
    const int tid  = threadIdx.x;
    const int wid  = tid >> 5;     // 0..7
    const int lane = tid & 31;
    const int bh   = blockIdx.x >> 2;
    const int qtr  = blockIdx.x & 3;

    __shared__ float sP[1024];     // stage-A partial dots (8 per token)
    __shared__ float sR[128];      // token rates
    __shared__ float sw[8];        // stage-E per-warp sums

    const size_t base = (size_t)bh * 8192;
    const float* Qb = Q + base;
    const float* Kb = K + base;
    const float* Vb = V + base;
    float*       Ob = out + base;

    // ---- Stage A: all 1024 partial dots, 4 slots per thread. Slot s:
    //      token = s>>3, cols = (s&7)*8 (2 float4 of Q + 2 of K, coalesced). ----
    #pragma unroll
    for (int i = 0; i < 4; ++i) {
        const int slot = tid + 256 * i;
        const int tok  = slot >> 3;
        const int f4   = (slot & 7) << 1;
        const float4* qr = reinterpret_cast<const float4*>(Qb + tok * 64);
        const float4* kr = reinterpret_cast<const float4*>(Kb + tok * 64);
        float4 q0 = qr[f4], q1 = qr[f4 + 1];
        float4 k0 = kr[f4], k1 = kr[f4 + 1];
        float a = q0.x * k0.x;
        a = fmaf(q0.y, k0.y, a); a = fmaf(q0.z, k0.z, a); a = fmaf(q0.w, k0.w, a);
        a = fmaf(q1.x, k1.x, a); a = fmaf(q1.y, k1.y, a);
        a = fmaf(q1.z, k1.z, a); a = fmaf(q1.w, k1.w, a);
        sP[slot] = a;
    }
    __syncthreads();

    // ---- Stage B: 128 threads finish the dots (2 LDS.128) + closed-form LIF. ----
    if (tid < 128) {
        const float4* p = reinterpret_cast<const float4*>(sP) + (tid << 1);
        float4 p0 = p[0], p1 = p[1];
        float J = ((p0.x + p0.y) + (p0.z + p0.w)) + ((p1.x + p1.y) + (p1.z + p1.w));
        sR[tid] = lif_rate_cf(J);
    }
    __syncthreads();

    // ---- Stage C: WTA over T=128, computed redundantly in EVERY warp
    //      (identical data + ops -> bitwise-identical y, NO barriers). ----
    float y[4];
    #pragma unroll
    for (int j = 0; j < 4; ++j) y[j] = sR[lane + 32 * j];

    for (int it = 0; it < 20; ++it) {
        float l = (y[0] + y[1]) + (y[2] + y[3]);
        #pragma unroll
        for (int off = 16; off; off >>= 1)
            l += __shfl_xor_sync(0xffffffffu, l, off);
        if (l == 0.0f) break;                       // S=0: identity for y in [0,1]
        bool same = true;
        #pragma unroll
        for (int j = 0; j < 4; ++j) {
            float ny = fminf(fmaxf(fmaf(3.0f, y[j], -0.9f * l), 0.0f), 1.0f);
            same &= (ny == y[j]);
            y[j] = ny;
        }
        if (__all_sync(0xffffffffu, same)) break;   // exact fixed point
    }

    // ---- Fast exit: all rates zero (uniform across warps AND across the 4
    //      CTAs of this bh — same inputs, same ops). Output exactly zero:
    //      store only this CTA's 2048-float quarter (2 STG.128/thread). ----
    {
        bool z4 = (y[0] == 0.0f) & (y[1] == 0.0f) & (y[2] == 0.0f) & (y[3] == 0.0f);
        if (__all_sync(0xffffffffu, z4)) {
            float4 zero4 = make_float4(0.f, 0.f, 0.f, 0.f);
            float4* o4 = reinterpret_cast<float4*>(Ob + qtr * 2048);
            o4[tid]       = zero4;
            o4[tid + 256] = zero4;
            return;
        }
    }

    // ================= slow path (correct for any input; redundant per CTA,
    //                   all CTAs of a bh produce bitwise-identical stores) ====

    // publish post-WTA rates so stage D can index them by token
    if (wid == 0) {
        #pragma unroll
        for (int j = 0; j < 4; ++j) sR[lane + 32 * j] = y[j];
    }
    __syncthreads();

    // ---- Stage D: J_v = rate * V over ALL 8192 units, 32 elems/thread.
    //      Thread covers half a token row: token = tid>>1, cols = (tid&1)*32. ----
    float z[32];
    {
        const int tok = tid >> 1;
        const float r = sR[tok];
        if (r != 0.0f) {
            const float4* vr = reinterpret_cast<const float4*>(Vb + tok * 64)
                             + ((tid & 1) << 3);
            #pragma unroll
            for (int i = 0; i < 8; ++i) {
                float4 v4 = vr[i];
                z[i * 4 + 0] = lif_rate_cf(r * v4.x);
                z[i * 4 + 1] = lif_rate_cf(r * v4.y);
                z[i * 4 + 2] = lif_rate_cf(r * v4.z);
                z[i * 4 + 3] = lif_rate_cf(r * v4.w);
            }
        } else {
            #pragma unroll
            for (int i = 0; i < 32; ++i) z[i] = 0.0f;
        }
    }

    // ---- Stage E: WTA over T*D=8192, block-wide, 32 values/thread. ----
    for (int it = 0; it < 20; ++it) {
        float l = 0.0f;
        #pragma unroll
        for (int i = 0; i < 32; ++i) l += z[i];
        #pragma unroll
        for (int off = 16; off; off >>= 1)
            l += __shfl_xor_sync(0xffffffffu, l, off);
        if (lane == 0) sw[wid] = l;
        __syncthreads();
        float S = sw[lane & 7];
        #pragma unroll
        for (int off = 4; off; off >>= 1)
            S += __shfl_xor_sync(0xffffffffu, S, off);
        if (S == 0.0f) break;            // all-zero: exact fixed point (uniform)
        int same = 1;
        #pragma unroll
        for (int i = 0; i < 32; ++i) {
            float nz = fminf(fmaxf(fmaf(3.0f, z[i], -0.9f * S), 0.0f), 1.0f);
            same &= (nz == z[i]);
            z[i] = nz;
        }
        if (__syncthreads_and(same)) break;   // barrier + block-uniform vote
    }

    // ---- Store: this thread's 32 contiguous elems (8 STG.128). All four
    //      CTAs of the bh write identical values — benign duplicates. ----
    {
        float4* o4 = reinterpret_cast<float4*>(Ob) + (tid << 3);
        #pragma unroll
        for (int i = 0; i < 8; ++i)
            o4[i] = make_float4(z[i * 4], z[i * 4 + 1], z[i * 4 + 2], z[i * 4 + 3]);
    }
}

extern "C" void kernel_launch(void* const* d_in, const int* in_sizes, int n_in,
                              void* d_out, int out_size) {
    const float* Q = (const float*)d_in[0];
    const float* K = (const float*)d_in[1];
    const float* V = (const float*)d_in[2];
    k_bio_fused<<<NBH * 4, 256>>>(Q, K, V, (float*)d_out);
}